// round 10
// baseline (speedup 1.0000x reference)
#include <cuda_runtime.h>
#include <cuda_bf16.h>
#include <math.h>

// Problem constants
#define NSITES 1024
#define NC6 64               // 6-site blocks: 2^6 codes
#define NC4 16               // 4-site tail block: 2^4 codes
#define NSTEPS 171           // 170 six-site + 1 four-site
// table entry layout (per code): 512 u32 = 128 uint4, B-fragment order
__device__ unsigned int g_table[(NC6 + NC4) * 512];   // 6-table then 4-table

// ---------------------------------------------------------------------------
// Precompute: block 0..63 -> 6-site products, block 64..79 -> 4-site products.
// Stores Y = P - I as bf16 B-fragments (deviation form for the B operand).
// ---------------------------------------------------------------------------
__global__ void build_table_kernel(const float* __restrict__ A) {
    __shared__ float M[2][32][32];
    __shared__ float P[2][32][32];
    const int tid = threadIdx.x;          // 1024 threads
    const int r = tid >> 5, c = tid & 31;

    M[0][r][c] = A[r * 32 + c];
    M[1][r][c] = A[1024 + r * 32 + c];
    __syncthreads();

    const bool is6 = blockIdx.x < NC6;
    const int code = is6 ? blockIdx.x : (blockIdx.x - NC6);
    const int nsit = is6 ? 6 : 4;

    P[0][r][c] = M[code & 1][r][c];
    __syncthreads();

    int cur = 0;
    for (int t = 1; t < nsit; t++) {
        const int bsel = (code >> t) & 1;
        float acc = 0.f;
        #pragma unroll
        for (int k = 0; k < 32; k++) acc += P[cur][r][k] * M[bsel][k][c];
        P[1 - cur][r][c] = acc;
        cur ^= 1;
        __syncthreads();
    }
    if (tid < 512) {
        const int l = tid >> 4;           // lane
        const int ridx = tid & 15;        // reg 0..15
        const int tig = l & 3, g = l >> 2;
        const int kc = ridx >> 3, nt = (ridx >> 1) & 3, h = ridx & 1;
        const int row = 16 * kc + 2 * tig + 8 * h;
        const int col = 8 * nt + g;
        const float lo = P[cur][row][col]     - (row     == col ? 1.f : 0.f);
        const float hi = P[cur][row + 1][col] - (row + 1 == col ? 1.f : 0.f);
        unsigned v;
        asm("cvt.rn.bf16x2.f32 %0, %1, %2;" : "=r"(v) : "f"(hi), "f"(lo));
        const int q = ridx >> 2, j = ridx & 3;
        g_table[blockIdx.x * 512 + q * 128 + l * 4 + j] = v;
    }
}

// ---------------------------------------------------------------------------
// Main kernel: ONE sample per warp, 28 warps/CTA, 1 CTA/SM.
// Flat software-pipelined loop over 171 precomputed block codes:
//   [t0,t1 preloaded] -> lds t2,t3 -> MMA kc0 -> MMA kc1 ->
//   lds t0,t1 (NEXT step, fills the MMA drain window) -> cvt a (next A)
// Per step:  M <- mma( bf16(M) , Y_code ) + M   ==  M @ (I + Y)   (C exact)
// ---------------------------------------------------------------------------
__device__ __forceinline__ void mma_bf16(float* d, const unsigned* a,
                                         unsigned b0, unsigned b1) {
    asm("mma.sync.aligned.m16n8k16.row.col.f32.bf16.bf16.f32 "
        "{%0,%1,%2,%3}, {%4,%5,%6,%7}, {%8,%9}, {%0,%1,%2,%3};"
        : "+f"(d[0]), "+f"(d[1]), "+f"(d[2]), "+f"(d[3])
        : "r"(a[0]), "r"(a[1]), "r"(a[2]), "r"(a[3]), "r"(b0), "r"(b1));
}

// Convert all 16 A fragments (reads post-step x; order matches MMA
// completion order: per mt, tiles nt0..nt3)
__device__ __forceinline__ void cvt_a(unsigned a[16], const float x[32]) {
    #pragma unroll
    for (int mt = 0; mt < 2; mt++)
        #pragma unroll
        for (int kc = 0; kc < 2; kc++)
            #pragma unroll
            for (int j = 0; j < 4; j++) {
                const int o = j >> 1, ih = j & 1;
                const int xi = mt * 16 + (2 * kc + o) * 4 + 2 * ih;
                asm("cvt.rn.bf16x2.f32 %0, %1, %2;"
                    : "=r"(a[mt * 8 + kc * 4 + j])
                    : "f"(x[xi + 1]), "f"(x[xi]));
            }
}

// 8 MMAs of one k-half; ta/tb are the two uint4 B tiles for this half
__device__ __forceinline__ void mma_half(float x[32], const unsigned a[16],
                                         int abase, uint4 ta, uint4 tb) {
    #pragma unroll
    for (int mt = 0; mt < 2; mt++) {
        const unsigned* av = a + mt * 8 + abase;
        mma_bf16(x + mt*16 + 0,  av, ta.x, ta.y);
        mma_bf16(x + mt*16 + 4,  av, ta.z, ta.w);
        mma_bf16(x + mt*16 + 8,  av, tb.x, tb.y);
        mma_bf16(x + mt*16 + 12, av, tb.z, tb.w);
    }
}

#define TAB_BYTES ((NC6 + NC4) * 512 * 4)     // 160 KB
#define NWARPS 28
#define MSK_BYTES (NWARPS * 32 * 4)           // 3.5 KB
#define CODE_STRIDE 176                        // 171 used + pad, 16B aligned
#define CODE_BYTES (NWARPS * CODE_STRIDE)      // ~4.8 KB
#define SMEM_BYTES (TAB_BYTES + MSK_BYTES + CODE_BYTES)
#define GRID 148
#define NTHREADS (NWARPS * 32)                 // 896 threads

__global__ void __launch_bounds__(NTHREADS, 1)
mps_kernel(const float* __restrict__ s, float* __restrict__ out) {
    extern __shared__ unsigned char smem_raw[];
    uint4* tab = reinterpret_cast<uint4*>(smem_raw);
    unsigned* msk = reinterpret_cast<unsigned*>(smem_raw + TAB_BYTES);
    unsigned char* codes = smem_raw + TAB_BYTES + MSK_BYTES;

    {   // cooperative copy of both tables into shared memory
        const uint4* gt = reinterpret_cast<const uint4*>(g_table);
        for (int i = threadIdx.x; i < (NC6 + NC4) * 128; i += NTHREADS)
            tab[i] = gt[i];
    }

    const int lane = threadIdx.x & 31;
    const int warp = threadIdx.x >> 5;
    // Balanced warp->sample map over all 148 SMs (28*148 = 4144 >= 4096)
    const int b = warp * GRID + blockIdx.x;
    const int g = lane >> 2, tig = lane & 3;

    // Prologue: masks -> smem, then flat code sequence -> smem (warp-private)
    if (b < 4096) {
        const float* srow = s + (size_t)b * NSITES;
        unsigned* mw = msk + warp * 32;
        #pragma unroll 8
        for (int j = 0; j < 32; j++)
            mw[j] = __ballot_sync(0xffffffffu, srow[j * 32 + lane] > 0.f);

        unsigned char* cw = codes + warp * CODE_STRIDE;
        for (int t = lane; t < NSTEPS; t += 32) {
            if (t < 170) {
                const int bit = 6 * t;
                const int w = bit >> 5, sh = bit & 31;
                const unsigned lo = mw[w];
                const unsigned hi = (w < 31) ? mw[w + 1] : 0u;
                cw[t] = (unsigned char)(__funnelshift_r(lo, hi, sh) & 63u);
            } else {
                cw[170] = (unsigned char)(NC6 + (mw[31] >> 28));  // 4-site tail
            }
        }
        if (lane == 0) cw[NSTEPS] = 0;     // safe prefetch target
    }
    __syncthreads();            // table ready
    if (b >= 4096) return;

    // Init M = I in C-fragment layout
    float x[32];
    #pragma unroll
    for (int mt = 0; mt < 2; mt++)
        #pragma unroll
        for (int nt = 0; nt < 4; nt++)
            #pragma unroll
            for (int i = 0; i < 4; i++) {
                const int row = g + 8 * (i >> 1) + 16 * mt;
                const int col = 8 * nt + 2 * tig + (i & 1);
                x[mt*16 + nt*4 + i] = (row == col) ? 1.f : 0.f;
            }

    const unsigned char* cw = codes + warp * CODE_STRIDE;

    // Pipeline prologue: A-fragments for step 0, kc0 B tiles for step 0
    unsigned a[16];
    cvt_a(a, x);
    const uint4* p = tab + (int)cw[0] * 128 + lane;
    uint4 t0 = p[0], t1 = p[32];

    // Flat software-pipelined main loop (codes[170] is the 4-site tail)
    #pragma unroll 3
    for (int k = 0; k < NSTEPS; k++) {
        const uint4* pn = tab + (int)cw[k + 1] * 128 + lane;
        const uint4 t2 = p[64], t3 = p[96];    // kc1 tiles (hidden by kc0)
        mma_half(x, a, 0, t0, t1);             // kc0
        mma_half(x, a, 4, t2, t3);             // kc1
        t0 = pn[0]; t1 = pn[32];               // prefetch next kc0 in drain
        cvt_a(a, x);                           // next step's A (dep on MMAs)
        p = pn;
    }

    // trace(M); pick this thread's diagonal elements
    float tr = 0.f;
    #pragma unroll
    for (int mt = 0; mt < 2; mt++)
        #pragma unroll
        for (int nt = 0; nt < 4; nt++)
            #pragma unroll
            for (int i = 0; i < 4; i++) {
                const int row = g + 8 * (i >> 1) + 16 * mt;
                const int col = 8 * nt + 2 * tig + (i & 1);
                if (row == col) tr += x[mt*16 + nt*4 + i];
            }
    #pragma unroll
    for (int off = 16; off; off >>= 1)
        tr += __shfl_xor_sync(0xffffffffu, tr, off);

    if (lane == 0) out[b] = logf(tr);
}

// ---------------------------------------------------------------------------
extern "C" void kernel_launch(void* const* d_in, const int* in_sizes, int n_in,
                              void* d_out, int out_size) {
    const float* s = (const float*)d_in[0];   // [4096, 1024] fp32
    const float* A = (const float*)d_in[1];   // [2, 32, 32] fp32
    float* out = (float*)d_out;               // [4096] fp32

    static bool attr_set = false;
    if (!attr_set) {
        cudaFuncSetAttribute(mps_kernel,
                             cudaFuncAttributeMaxDynamicSharedMemorySize,
                             SMEM_BYTES);
        attr_set = true;
    }

    build_table_kernel<<<NC6 + NC4, 1024>>>(A);
    mps_kernel<<<GRID, NTHREADS, SMEM_BYTES>>>(s, out);
}